// round 3
// baseline (speedup 1.0000x reference)
#include <cuda_runtime.h>

// SimpleRNN: 2-layer tanh RNN, B=8192, S=512, H=16, INPUT=1, fc on last step.
// Strategy: 8 lanes per batch element, each lane owns 2 hidden rows of both
// layers. Weights register-resident as packed f32x2; matvecs use
// fma.rn.f32x2 (SASS FFMA2, 2 MACs/instr). Hidden-state exchange via padded
// shared memory (conflict-free), one __syncwarp per timestep.

#define BATCH   8192
#define SEQ     512
#define HID     16
#define NB      32        // batches per block
#define THREADS 256       // 8 lanes per batch
#define HPAD    36        // floats per batch row in smem (bank-conflict-free)

typedef unsigned long long u64;

__device__ __forceinline__ u64 fma2(u64 a, u64 b, u64 c) {
    u64 d;
    asm("fma.rn.f32x2 %0, %1, %2, %3;" : "=l"(d) : "l"(a), "l"(b), "l"(c));
    return d;
}
__device__ __forceinline__ u64 pack2(float lo, float hi) {
    u64 d;
    asm("mov.b64 %0, {%1, %2};" : "=l"(d) : "f"(lo), "f"(hi));
    return d;
}
__device__ __forceinline__ void unpack2(u64 v, float& lo, float& hi) {
    asm("mov.b64 {%0, %1}, %2;" : "=f"(lo), "=f"(hi) : "l"(v));
}
// tanh(x) = 1 - 2/(exp(2x)+1): 2 MUFU + ~4 fma-pipe ops, abs err ~1e-6.
__device__ __forceinline__ float tanh_fast(float v) {
    float e = __expf(2.0f * v);
    return 1.0f - __fdividef(2.0f, e + 1.0f);
}

__global__ __launch_bounds__(THREADS, 1)
void rnn2_kernel(const float* __restrict__ x,
                 const float* __restrict__ Wih0, const float* __restrict__ Whh0,
                 const float* __restrict__ bih0, const float* __restrict__ bhh0,
                 const float* __restrict__ Wih1, const float* __restrict__ Whh1,
                 const float* __restrict__ bih1, const float* __restrict__ bhh1,
                 const float* __restrict__ Wfc,  const float* __restrict__ bfc,
                 float* __restrict__ out)
{
    __shared__ float hbuf[NB][HPAD];   // [0..15]=h0, [16..31]=h1 per batch

    const int tid = threadIdx.x;
    const int lb  = tid >> 3;          // local batch index 0..31
    const int k   = tid & 7;           // row-pair owner 0..7
    const int b   = blockIdx.x * NB + lb;
    const int ra  = 2 * k, rb = 2 * k + 1;

    // ---- weights to registers (packed pairs along j) ----
    u64 whh0a[8], whh0b[8], wih1a[8], wih1b[8], whh1a[8], whh1b[8];
#pragma unroll
    for (int j = 0; j < 8; j++) {
        whh0a[j] = *(const u64*)(Whh0 + ra * HID + 2 * j);
        whh0b[j] = *(const u64*)(Whh0 + rb * HID + 2 * j);
        wih1a[j] = *(const u64*)(Wih1 + ra * HID + 2 * j);
        wih1b[j] = *(const u64*)(Wih1 + rb * HID + 2 * j);
        whh1a[j] = *(const u64*)(Whh1 + ra * HID + 2 * j);
        whh1b[j] = *(const u64*)(Whh1 + rb * HID + 2 * j);
    }
    const float wia = Wih0[ra], wib = Wih0[rb];
    const float c0a = bih0[ra] + bhh0[ra], c0b = bih0[rb] + bhh0[rb];
    const float c1a = bih1[ra] + bhh1[ra], c1b = bih1[rb] + bhh1[rb];

    float* hrow = hbuf[lb];

    // init: h0 packed regs = 0; h1 region of smem = 0 (read at t=0)
    u64 h0p[8];
#pragma unroll
    for (int j = 0; j < 8; j++) h0p[j] = 0ull;
    *(float2*)(hrow + 16 + 2 * k) = make_float2(0.f, 0.f);
    __syncwarp();

    const float* xb = x + (size_t)b * SEQ;
    float xc = xb[0];
    float h1a = 0.f, h1b = 0.f;

#pragma unroll 1
    for (int t = 0; t < SEQ; t++) {
        // ---- layer 0: rows ra, rb ----
        u64 acca = pack2(fmaf(wia, xc, c0a), 0.f);
        u64 accb = pack2(fmaf(wib, xc, c0b), 0.f);
#pragma unroll
        for (int j = 0; j < 8; j++) {
            acca = fma2(whh0a[j], h0p[j], acca);
            accb = fma2(whh0b[j], h0p[j], accb);
        }
        float la, ha, lc, hc;
        unpack2(acca, la, ha);
        unpack2(accb, lc, hc);
        float h0a = tanh_fast(la + ha);
        float h0b = tanh_fast(lc + hc);

        // prefetch next x (branchless, uniform)
        int tn   = (t + 1 < SEQ) ? t + 1 : SEQ - 1;
        float xn = xb[tn];

        // publish new h0; previous h1 (stored end of last iter) becomes
        // visible after the same syncwarp.
        *(float2*)(hrow + 2 * k) = make_float2(h0a, h0b);
        __syncwarp();

        u64 h1p[8];
#pragma unroll
        for (int j = 0; j < 8; j++) h0p[j] = *(const u64*)(hrow + 2 * j);
#pragma unroll
        for (int j = 0; j < 8; j++) h1p[j] = *(const u64*)(hrow + 16 + 2 * j);

        // ---- layer 1: rows ra, rb ----
        u64 a1 = pack2(c1a, 0.f);
        u64 b1 = pack2(c1b, 0.f);
#pragma unroll
        for (int j = 0; j < 8; j++) {
            a1 = fma2(wih1a[j], h0p[j], a1);
            b1 = fma2(wih1b[j], h0p[j], b1);
        }
#pragma unroll
        for (int j = 0; j < 8; j++) {
            a1 = fma2(whh1a[j], h1p[j], a1);
            b1 = fma2(whh1b[j], h1p[j], b1);
        }
        unpack2(a1, la, ha);
        unpack2(b1, lc, hc);
        h1a = tanh_fast(la + ha);
        h1b = tanh_fast(lc + hc);
        *(float2*)(hrow + 16 + 2 * k) = make_float2(h1a, h1b);

        xc = xn;
    }

    // ---- fc on last h1: partial over own 2 rows, reduce across 8 lanes ----
    float p = fmaf(Wfc[ra], h1a, Wfc[rb] * h1b);
    p += __shfl_down_sync(0xffffffffu, p, 4, 8);
    p += __shfl_down_sync(0xffffffffu, p, 2, 8);
    p += __shfl_down_sync(0xffffffffu, p, 1, 8);
    if (k == 0) out[b] = p + bfc[0];
}

extern "C" void kernel_launch(void* const* d_in, const int* in_sizes, int n_in,
                              void* d_out, int out_size)
{
    const float* x    = (const float*)d_in[0];
    const float* Wih0 = (const float*)d_in[1];
    const float* Whh0 = (const float*)d_in[2];
    const float* bih0 = (const float*)d_in[3];
    const float* bhh0 = (const float*)d_in[4];
    const float* Wih1 = (const float*)d_in[5];
    const float* Whh1 = (const float*)d_in[6];
    const float* bih1 = (const float*)d_in[7];
    const float* bhh1 = (const float*)d_in[8];
    const float* Wfc  = (const float*)d_in[9];
    const float* bfc  = (const float*)d_in[10];
    float* out = (float*)d_out;

    rnn2_kernel<<<BATCH / NB, THREADS>>>(x, Wih0, Whh0, bih0, bhh0,
                                         Wih1, Whh1, bih1, bhh1,
                                         Wfc, bfc, out);
}

// round 4
// speedup vs baseline: 1.1127x; 1.1127x over previous
#include <cuda_runtime.h>

// SimpleRNN: 2-layer tanh RNN, B=8192, S=512, H=16, INPUT=1, fc on last step.
// R4: occupancy-targeted restructure. 8 lanes/batch, 2 hidden rows per lane.
// Whh0 lives in shared memory (padded per-lane chunks, conflict-free broadcast
// loads) to cut 32 registers; wih1/whh1 stay register-resident as packed
// f32x2. h-vector exchange via padded smem with LDS.128 reads. Forced
// <=128 regs via __launch_bounds__(256,2) -> 2 blocks/SM -> 4 warps/SMSP,
// single wave.

#define BATCH   8192
#define SEQ     512
#define HID     16
#define NB      32        // batches per block
#define THREADS 256       // 8 lanes per batch
#define HPAD    36        // floats per batch row in smem (bank-stagger pad)
#define WPAD    36        // floats per lane weight chunk (32 data + 4 pad)

typedef unsigned long long u64;

__device__ __forceinline__ u64 fma2(u64 a, u64 b, u64 c) {
    u64 d;
    asm("fma.rn.f32x2 %0, %1, %2, %3;" : "=l"(d) : "l"(a), "l"(b), "l"(c));
    return d;
}
__device__ __forceinline__ u64 pack2(float lo, float hi) {
    u64 d;
    asm("mov.b64 %0, {%1, %2};" : "=l"(d) : "f"(lo), "f"(hi));
    return d;
}
__device__ __forceinline__ void unpack2(u64 v, float& lo, float& hi) {
    asm("mov.b64 {%0, %1}, %2;" : "=f"(lo), "=f"(hi) : "l"(v));
}
// tanh(x) = 1 - 2/(exp(2x)+1): 2 MUFU + ~4 fma-pipe ops, abs err ~1e-6.
__device__ __forceinline__ float tanh_fast(float v) {
    float e = __expf(2.0f * v);
    return 1.0f - __fdividef(2.0f, e + 1.0f);
}

__global__ __launch_bounds__(THREADS, 2)
void rnn2_kernel(const float* __restrict__ x,
                 const float* __restrict__ Wih0, const float* __restrict__ Whh0,
                 const float* __restrict__ bih0, const float* __restrict__ bhh0,
                 const float* __restrict__ Wih1, const float* __restrict__ Whh1,
                 const float* __restrict__ bih1, const float* __restrict__ bhh1,
                 const float* __restrict__ Wfc,  const float* __restrict__ bfc,
                 float* __restrict__ out)
{
    __shared__ float hbuf[NB][HPAD];   // [0..15]=h0, [16..31]=h1 per batch
    __shared__ float whh0s[8 * WPAD];  // per-lane chunk k: rows 2k,2k+1 (32 floats)

    const int tid = threadIdx.x;
    const int lb  = tid >> 3;          // local batch index 0..31
    const int k   = tid & 7;           // row-pair owner 0..7
    const int b   = blockIdx.x * NB + lb;
    const int ra  = 2 * k, rb = 2 * k + 1;

    // ---- stage Whh0 into smem (padded per-lane chunks) ----
    for (int idx = tid; idx < 8 * 32; idx += THREADS) {
        int kk = idx >> 5;            // chunk
        int e  = idx & 31;            // element within chunk (row-major 2x16)
        whh0s[kk * WPAD + e] = Whh0[(2 * kk) * HID + e];  // rows 2kk,2kk+1 contiguous
    }

    // ---- layer-1 weights to registers (packed pairs along j) ----
    u64 wih1a[8], wih1b[8], whh1a[8], whh1b[8];
#pragma unroll
    for (int j = 0; j < 8; j++) {
        wih1a[j] = *(const u64*)(Wih1 + ra * HID + 2 * j);
        wih1b[j] = *(const u64*)(Wih1 + rb * HID + 2 * j);
        whh1a[j] = *(const u64*)(Whh1 + ra * HID + 2 * j);
        whh1b[j] = *(const u64*)(Whh1 + rb * HID + 2 * j);
    }
    const float wia = Wih0[ra], wib = Wih0[rb];
    const float c0a = bih0[ra] + bhh0[ra], c0b = bih0[rb] + bhh0[rb];
    const float c1a = bih1[ra] + bhh1[ra], c1b = bih1[rb] + bhh1[rb];

    float* hrow = hbuf[lb];
    ulonglong2* hv = (ulonglong2*)hrow;          // [0..3]=h0 vec, [4..7]=h1 vec
    const ulonglong2* wk = (const ulonglong2*)(whh0s + k * WPAD); // [0..3]=row a, [4..7]=row b

    // init: h0 packed regs = 0; h1 region of smem = 0 (read at t=0)
    u64 h0p[8];
#pragma unroll
    for (int j = 0; j < 8; j++) h0p[j] = 0ull;
    *(float2*)(hrow + 16 + 2 * k) = make_float2(0.f, 0.f);
    __syncthreads();   // whh0s staged + h1 zeros visible

    const float* xb = x + (size_t)b * SEQ;
    float xc = xb[0];
    float h1a = 0.f, h1b = 0.f;

#pragma unroll 1
    for (int t = 0; t < SEQ; t++) {
        // ---- layer 0: rows ra, rb; weights streamed from smem ----
        u64 acca = pack2(fmaf(wia, xc, c0a), 0.f);
        u64 accb = pack2(fmaf(wib, xc, c0b), 0.f);
#pragma unroll
        for (int g = 0; g < 4; g++) {
            ulonglong2 wa = wk[g];
            ulonglong2 wb = wk[4 + g];
            acca = fma2(wa.x, h0p[2 * g],     acca);
            accb = fma2(wb.x, h0p[2 * g],     accb);
            acca = fma2(wa.y, h0p[2 * g + 1], acca);
            accb = fma2(wb.y, h0p[2 * g + 1], accb);
        }
        float la, ha, lc, hc;
        unpack2(acca, la, ha);
        unpack2(accb, lc, hc);
        float h0a = tanh_fast(la + ha);
        float h0b = tanh_fast(lc + hc);

        // prefetch next x (branchless, uniform)
        int tn   = (t + 1 < SEQ) ? t + 1 : SEQ - 1;
        float xn = xb[tn];

        // publish new h0; previous h1 (stored end of last iter) becomes
        // visible after the same syncwarp.
        *(float2*)(hrow + 2 * k) = make_float2(h0a, h0b);
        __syncwarp();

        // refresh full h0 vector (used by layer1 now AND layer0 next iter)
        {
            ulonglong2 q0 = hv[0], q1 = hv[1], q2 = hv[2], q3 = hv[3];
            h0p[0] = q0.x; h0p[1] = q0.y; h0p[2] = q1.x; h0p[3] = q1.y;
            h0p[4] = q2.x; h0p[5] = q2.y; h0p[6] = q3.x; h0p[7] = q3.y;
        }

        // ---- layer 1: rows ra, rb ----
        u64 a1 = pack2(c1a, 0.f);
        u64 b1 = pack2(c1b, 0.f);
#pragma unroll
        for (int j = 0; j < 8; j++) {
            a1 = fma2(wih1a[j], h0p[j], a1);
            b1 = fma2(wih1b[j], h0p[j], b1);
        }
        // h1 vector: transient, loaded late to cap liveness
        {
            ulonglong2 q4 = hv[4], q5 = hv[5];
            a1 = fma2(whh1a[0], q4.x, a1);  b1 = fma2(whh1b[0], q4.x, b1);
            a1 = fma2(whh1a[1], q4.y, a1);  b1 = fma2(whh1b[1], q4.y, b1);
            a1 = fma2(whh1a[2], q5.x, a1);  b1 = fma2(whh1b[2], q5.x, b1);
            a1 = fma2(whh1a[3], q5.y, a1);  b1 = fma2(whh1b[3], q5.y, b1);
            ulonglong2 q6 = hv[6], q7 = hv[7];
            a1 = fma2(whh1a[4], q6.x, a1);  b1 = fma2(whh1b[4], q6.x, b1);
            a1 = fma2(whh1a[5], q6.y, a1);  b1 = fma2(whh1b[5], q6.y, b1);
            a1 = fma2(whh1a[6], q7.x, a1);  b1 = fma2(whh1b[6], q7.x, b1);
            a1 = fma2(whh1a[7], q7.y, a1);  b1 = fma2(whh1b[7], q7.y, b1);
        }
        unpack2(a1, la, ha);
        unpack2(b1, lc, hc);
        h1a = tanh_fast(la + ha);
        h1b = tanh_fast(lc + hc);
        *(float2*)(hrow + 16 + 2 * k) = make_float2(h1a, h1b);

        xc = xn;
    }

    // ---- fc on last h1: partial over own 2 rows, reduce across 8 lanes ----
    float p = fmaf(Wfc[ra], h1a, Wfc[rb] * h1b);
    p += __shfl_down_sync(0xffffffffu, p, 4, 8);
    p += __shfl_down_sync(0xffffffffu, p, 2, 8);
    p += __shfl_down_sync(0xffffffffu, p, 1, 8);
    if (k == 0) out[b] = p + bfc[0];
}

extern "C" void kernel_launch(void* const* d_in, const int* in_sizes, int n_in,
                              void* d_out, int out_size)
{
    const float* x    = (const float*)d_in[0];
    const float* Wih0 = (const float*)d_in[1];
    const float* Whh0 = (const float*)d_in[2];
    const float* bih0 = (const float*)d_in[3];
    const float* bhh0 = (const float*)d_in[4];
    const float* Wih1 = (const float*)d_in[5];
    const float* Whh1 = (const float*)d_in[6];
    const float* bih1 = (const float*)d_in[7];
    const float* bhh1 = (const float*)d_in[8];
    const float* Wfc  = (const float*)d_in[9];
    const float* bfc  = (const float*)d_in[10];
    float* out = (float*)d_out;

    rnn2_kernel<<<BATCH / NB, THREADS>>>(x, Wih0, Whh0, bih0, bhh0,
                                         Wih1, Whh1, bih1, bhh1,
                                         Wfc, bfc, out);
}

// round 5
// speedup vs baseline: 1.4009x; 1.2590x over previous
#include <cuda_runtime.h>

// SimpleRNN: 2-layer tanh RNN, B=8192, S=512, H=16, INPUT=1, fc on last step.
// R5: all weights register-resident (no per-step weight LDS); h-vectors
// streamed from double-buffered smem in 16B windows; layer-1 lagged one step
// so both layer matvecs run concurrently (4 independent accum chains);
// one __syncwarp per step; tanh via MUFU (tanh.approx.f32).

#define BATCH   8192
#define SEQ     512
#define HID     16
#define NB      32        // batches per block
#define THREADS 256       // 8 lanes per batch
#define HROW    40        // floats per batch row (16 h0 + 16 h1 + 8 pad)

typedef unsigned long long u64;

__device__ __forceinline__ u64 fma2(u64 a, u64 b, u64 c) {
    u64 d;
    asm("fma.rn.f32x2 %0, %1, %2, %3;" : "=l"(d) : "l"(a), "l"(b), "l"(c));
    return d;
}
__device__ __forceinline__ u64 pack2(float lo, float hi) {
    u64 d;
    asm("mov.b64 %0, {%1, %2};" : "=l"(d) : "f"(lo), "f"(hi));
    return d;
}
__device__ __forceinline__ void unpack2(u64 v, float& lo, float& hi) {
    asm("mov.b64 {%0, %1}, %2;" : "=f"(lo), "=f"(hi) : "l"(v));
}
__device__ __forceinline__ float tanh_mufu(float v) {
    float r;
    asm("tanh.approx.f32 %0, %1;" : "=f"(r) : "f"(v));
    return r;
}

__global__ __launch_bounds__(THREADS, 2)
void rnn2_kernel(const float* __restrict__ x,
                 const float* __restrict__ Wih0, const float* __restrict__ Whh0,
                 const float* __restrict__ bih0, const float* __restrict__ bhh0,
                 const float* __restrict__ Wih1, const float* __restrict__ Whh1,
                 const float* __restrict__ bih1, const float* __restrict__ bhh1,
                 const float* __restrict__ Wfc,  const float* __restrict__ bfc,
                 float* __restrict__ out)
{
    // double-buffered hidden state: [parity][batch][h0(16) h1(16) pad(8)]
    __shared__ float hbuf[2][NB][HROW];

    const int tid = threadIdx.x;
    const int lb  = tid >> 3;          // local batch 0..31 (quarter-warp = same lb)
    const int k   = tid & 7;           // row-pair owner 0..7
    const int b   = blockIdx.x * NB + lb;
    const int ra  = 2 * k, rb = 2 * k + 1;

    // ---- all weights to registers (packed f32x2 along j) ----
    u64 whh0a[8], whh0b[8], wih1a[8], wih1b[8], whh1a[8], whh1b[8];
#pragma unroll
    for (int j = 0; j < 8; j++) {
        whh0a[j] = *(const u64*)(Whh0 + ra * HID + 2 * j);
        whh0b[j] = *(const u64*)(Whh0 + rb * HID + 2 * j);
        wih1a[j] = *(const u64*)(Wih1 + ra * HID + 2 * j);
        wih1b[j] = *(const u64*)(Wih1 + rb * HID + 2 * j);
        whh1a[j] = *(const u64*)(Whh1 + ra * HID + 2 * j);
        whh1b[j] = *(const u64*)(Whh1 + rb * HID + 2 * j);
    }
    const float wia = Wih0[ra], wib = Wih0[rb];
    const float c0a = bih0[ra] + bhh0[ra], c0b = bih0[rb] + bhh0[rb];
    const float c1a = bih1[ra] + bhh1[ra], c1b = bih1[rb] + bhh1[rb];

    // init parity-0 buffer (h0 = h1 = 0)
    *(float2*)(&hbuf[0][lb][2 * k])      = make_float2(0.f, 0.f);
    *(float2*)(&hbuf[0][lb][16 + 2 * k]) = make_float2(0.f, 0.f);
    __syncwarp();

    const float* xb = x + (size_t)b * SEQ;
    float xc = xb[0];
    float h1a = 0.f, h1b = 0.f;

    // 513 iterations: step t computes h0(t) [t<SEQ] and h1(t-1) [t>0].
#pragma unroll 1
    for (int t = 0; t <= SEQ; t++) {
        const int p = t & 1;
        const float* src = &hbuf[p][lb][0];
        float*       dst = &hbuf[p ^ 1][lb][0];

        // prefetch next x (clamped)
        int tn   = (t + 1 < SEQ) ? t + 1 : SEQ - 1;
        float xn = xb[tn];

        // 4 independent accumulator chains
        u64 a0 = pack2(fmaf(wia, xc, c0a), 0.f);
        u64 b0 = pack2(fmaf(wib, xc, c0b), 0.f);
        u64 a1 = pack2(c1a, 0.f);
        u64 b1 = pack2(c1b, 0.f);

        // stream h0(t-1): feeds layer0 (whh0) and layer1 (wih1)
#pragma unroll
        for (int g = 0; g < 4; g++) {
            ulonglong2 q = ((const ulonglong2*)src)[g];
            a0 = fma2(whh0a[2 * g],     q.x, a0);
            b0 = fma2(whh0b[2 * g],     q.x, b0);
            a1 = fma2(wih1a[2 * g],     q.x, a1);
            b1 = fma2(wih1b[2 * g],     q.x, b1);
            a0 = fma2(whh0a[2 * g + 1], q.y, a0);
            b0 = fma2(whh0b[2 * g + 1], q.y, b0);
            a1 = fma2(wih1a[2 * g + 1], q.y, a1);
            b1 = fma2(wih1b[2 * g + 1], q.y, b1);
        }
        // stream h1(t-2): feeds layer1 (whh1)
#pragma unroll
        for (int g = 0; g < 4; g++) {
            ulonglong2 q = ((const ulonglong2*)(src + 16))[g];
            a1 = fma2(whh1a[2 * g],     q.x, a1);
            b1 = fma2(whh1b[2 * g],     q.x, b1);
            a1 = fma2(whh1a[2 * g + 1], q.y, a1);
            b1 = fma2(whh1b[2 * g + 1], q.y, b1);
        }

        float la, ha, lc, hc;
        unpack2(a0, la, ha);
        unpack2(b0, lc, hc);
        float h0a = tanh_mufu(la + ha);
        float h0b = tanh_mufu(lc + hc);

        unpack2(a1, la, ha);
        unpack2(b1, lc, hc);
        h1a = tanh_mufu(la + ha);
        h1b = tanh_mufu(lc + hc);
        if (t == 0) { h1a = 0.f; h1b = 0.f; }   // h1(-1) = 0 (initial state)

        *(float2*)(dst + 2 * k)      = make_float2(h0a, h0b);
        *(float2*)(dst + 16 + 2 * k) = make_float2(h1a, h1b);
        __syncwarp();

        xc = xn;
    }

    // ---- fc on h1(SEQ-1): partial over own 2 rows, reduce across 8 lanes ----
    float p = fmaf(Wfc[ra], h1a, Wfc[rb] * h1b);
    p += __shfl_down_sync(0xffffffffu, p, 4, 8);
    p += __shfl_down_sync(0xffffffffu, p, 2, 8);
    p += __shfl_down_sync(0xffffffffu, p, 1, 8);
    if (k == 0) out[b] = p + bfc[0];
}

extern "C" void kernel_launch(void* const* d_in, const int* in_sizes, int n_in,
                              void* d_out, int out_size)
{
    const float* x    = (const float*)d_in[0];
    const float* Wih0 = (const float*)d_in[1];
    const float* Whh0 = (const float*)d_in[2];
    const float* bih0 = (const float*)d_in[3];
    const float* bhh0 = (const float*)d_in[4];
    const float* Wih1 = (const float*)d_in[5];
    const float* Whh1 = (const float*)d_in[6];
    const float* bih1 = (const float*)d_in[7];
    const float* bhh1 = (const float*)d_in[8];
    const float* Wfc  = (const float*)d_in[9];
    const float* bfc  = (const float*)d_in[10];
    float* out = (float*)d_out;

    rnn2_kernel<<<BATCH / NB, THREADS>>>(x, Wih0, Whh0, bih0, bhh0,
                                         Wih1, Whh1, bih1, bhh1,
                                         Wfc, bfc, out);
}